// round 7
// baseline (speedup 1.0000x reference)
#include <cuda_runtime.h>
#include <cuda_bf16.h>
#include <math_constants.h>
#include <cstdint>

// ---------------------------------------------------------------------------
// Problem constants
// ---------------------------------------------------------------------------
#define BATCH   8
#define SEQ     1024
#define DIM     768
#define HEADS   12
#define HDIM    64
#define MROWS   (BATCH * SEQ)        // 8192
#define QKVCOLS (3 * DIM)            // 2304

// K-pair permutation within groups of 8: storage pos of k: k<4 -> 2k, else 2(k-4)+1.
// All MMA K-dimensions use this layout so fragment pairs (t4, t4+4) are adjacent.

// Scratch (device globals per allocation rules)
__device__ float g_qkv[MROWS * QKVCOLS];     // tf32 bits, N-cols pair-permuted
__device__ float g_attn[MROWS * DIM];        // tf32 bits, cols pair-permuted
__device__ float g_xt[MROWS * DIM];          // x tf32 bits, k pair-permuted
__device__ float g_w1[QKVCOLS * DIM];        // w_qkv^T [n][k] tf32, k pair-permuted
__device__ float g_w2[DIM * DIM];            // w_proj^T [n][k] tf32, k pair-permuted

// ---------------------------------------------------------------------------
// helpers
// ---------------------------------------------------------------------------
__device__ __forceinline__ uint32_t f2tf32(float x) {
    uint32_t r;
    asm("cvt.rna.tf32.f32 %0, %1;" : "=r"(r) : "f"(x));
    return r;
}
__device__ __forceinline__ float fexp2(float x) {
    float y;
    asm("ex2.approx.f32 %0, %1;" : "=f"(y) : "f"(x));
    return y;
}
__device__ __forceinline__ void mma_tf32(float c[4],
                                         uint32_t a0, uint32_t a1, uint32_t a2, uint32_t a3,
                                         uint32_t b0, uint32_t b1) {
    asm volatile(
        "mma.sync.aligned.m16n8k8.row.col.f32.tf32.tf32.f32 "
        "{%0,%1,%2,%3}, {%4,%5,%6,%7}, {%8,%9}, {%0,%1,%2,%3};\n"
        : "+f"(c[0]), "+f"(c[1]), "+f"(c[2]), "+f"(c[3])
        : "r"(a0), "r"(a1), "r"(a2), "r"(a3), "r"(b0), "r"(b1));
}
__device__ __forceinline__ void cp16(uint32_t dst_smem, const void* src) {
    asm volatile("cp.async.cg.shared.global [%0], [%1], 16;\n"
                 :: "r"(dst_smem), "l"(src) : "memory");
}
__device__ __forceinline__ void cp_commit() {
    asm volatile("cp.async.commit_group;\n" ::: "memory");
}
__device__ __forceinline__ void cp_wait0() {
    asm volatile("cp.async.wait_group 0;\n" ::: "memory");
}
__host__ __device__ __forceinline__ int kperm(int k8) {   // pos within group of 8
    return (k8 < 4) ? 2 * k8 : 2 * (k8 - 4) + 1;
}

// ---------------------------------------------------------------------------
// prep: tf32 convert + k-pair permute (flat; rows are multiples of 8)
// ---------------------------------------------------------------------------
__global__ __launch_bounds__(256)
void cvt_tf32_perm_kernel(const float* __restrict__ in, float* __restrict__ out, int n4) {
    int i = blockIdx.x * 256 + threadIdx.x;
    if (i < n4) {
        float4 v = reinterpret_cast<const float4*>(in)[i];
        int base = 4 * i;
        int g8 = base & ~7;
        int off = base & 7;            // 0 or 4
        int p0 = g8 + ((off == 0) ? 0 : 1);
        uint32_t* o = reinterpret_cast<uint32_t*>(out);
        o[p0 + 0] = f2tf32(v.x);
        o[p0 + 2] = f2tf32(v.y);
        o[p0 + 4] = f2tf32(v.z);
        o[p0 + 6] = f2tf32(v.w);
    }
}

// prep: w[k][n] -> wt[n][k] tf32, output k pair-permuted
__global__ __launch_bounds__(256)
void transpose_tf32_perm_kernel(const float* __restrict__ w, float* __restrict__ wt,
                                int K, int N) {
    __shared__ float s[32][33];
    const int kb = blockIdx.y * 32;
    const int nb = blockIdx.x * 32;
    const int r = threadIdx.x >> 3;
    const int c = (threadIdx.x & 7) * 4;

    float4 v = *reinterpret_cast<const float4*>(w + (size_t)(kb + r) * N + nb + c);
    s[r][c + 0] = v.x; s[r][c + 1] = v.y; s[r][c + 2] = v.z; s[r][c + 3] = v.w;
    __syncthreads();

    uint32_t* orow = reinterpret_cast<uint32_t*>(wt + (size_t)(nb + r) * K);
    #pragma unroll
    for (int j = 0; j < 4; ++j) {
        int kk = c + j;
        int pos = kb + (kk & ~7) + kperm(kk & 7);
        orow[pos] = f2tf32(s[kk][r]);
    }
}

// ---------------------------------------------------------------------------
// TF32 mma.sync GEMM + bias.  A[m][k] and B[n][k] both tf32 bits, k-permuted.
// Block 128x128, 4 warps (2x2), warp 64x64, BK=32, cp.async double-buffered.
// Fragment loads are LDS.64 (stride 40 -> conflict-free), double-buffered
// across the 4 k-steps to overlap with MMA issue.
// permute_out: write output cols pair-permuted as tf32 bits (for MMA consumers)
// ---------------------------------------------------------------------------
#define GA_LD 40
#define G_ABW (128 * GA_LD)                 // 5120 words per buffer
#define GEMM_SMEM_BYTES (4 * G_ABW * 4)     // A0,A1,B0,B1 = 81920 B

__global__ __launch_bounds__(128, 2)
void gemm_tf32_kernel(const float* __restrict__ A,
                      const float* __restrict__ B,
                      const float* __restrict__ bias,
                      float* __restrict__ C,
                      int M, int N, int K, int permute_out) {
    extern __shared__ uint32_t gsm[];
    const uint32_t sbytes = (uint32_t)__cvta_generic_to_shared(gsm);

    const int tid  = threadIdx.x;
    const int lane = tid & 31;
    const int wid  = tid >> 5;
    const int wr   = wid >> 1;
    const int wc   = wid & 1;
    const int g    = lane >> 2;
    const int t4   = lane & 3;

    const int bRow = blockIdx.y * 128;
    const int bCol = blockIdx.x * 128;

    auto issue_tile = [&](int buf, int kb) {
        const uint32_t abase = sbytes + (uint32_t)buf * G_ABW * 4;
        const uint32_t bbase = sbytes + (uint32_t)(2 + buf) * G_ABW * 4;
        #pragma unroll
        for (int i = 0; i < 8; ++i) {
            int ch = tid + i * 128;
            int r = ch >> 3, k4 = (ch & 7) * 4;     // 128 rows x 8 chunks
            cp16(abase + (uint32_t)(r * GA_LD + k4) * 4,
                 A + (size_t)(bRow + r) * K + kb + k4);
            cp16(bbase + (uint32_t)(r * GA_LD + k4) * 4,
                 B + (size_t)(bCol + r) * K + kb + k4);
        }
        cp_commit();
    };

    float acc[4][8][4];
    #pragma unroll
    for (int mt = 0; mt < 4; ++mt)
        #pragma unroll
        for (int nt = 0; nt < 8; ++nt)
            #pragma unroll
            for (int r = 0; r < 4; ++r) acc[mt][nt][r] = 0.0f;

    uint2 afb[2][4][2];   // [buf][mt][{row g, row g+8}] -> (a0,a2)/(a1,a3)
    uint2 bfb[2][8];      // [buf][nt] -> (b0,b1)

    const int NK = K / 32;
    issue_tile(0, 0);

    for (int t = 0; t < NK; ++t) {
        cp_wait0();
        __syncthreads();                         // buffer t ready; compute t-1 done
        if (t + 1 < NK) issue_tile((t + 1) & 1, (t + 1) * 32);

        const uint32_t* Ab = gsm + (t & 1) * G_ABW;
        const uint32_t* Bb = gsm + (2 + (t & 1)) * G_ABW;

        auto load_frag = [&](int ks, uint2 af[4][2], uint2 bf[8]) {
            const int k2 = ks * 8 + 2 * t4;
            #pragma unroll
            for (int mt = 0; mt < 4; ++mt) {
                int base = (wr * 64 + mt * 16 + g) * GA_LD + k2;
                af[mt][0] = *reinterpret_cast<const uint2*>(&Ab[base]);
                af[mt][1] = *reinterpret_cast<const uint2*>(&Ab[base + 8 * GA_LD]);
            }
            #pragma unroll
            for (int nt = 0; nt < 8; ++nt) {
                int base = (wc * 64 + nt * 8 + g) * GA_LD + k2;
                bf[nt] = *reinterpret_cast<const uint2*>(&Bb[base]);
            }
        };

        load_frag(0, afb[0], bfb[0]);
        #pragma unroll
        for (int ks = 0; ks < 4; ++ks) {
            const int cur = ks & 1;
            if (ks < 3) load_frag(ks + 1, afb[cur ^ 1], bfb[cur ^ 1]);
            #pragma unroll
            for (int nt = 0; nt < 8; ++nt)
                #pragma unroll
                for (int mt = 0; mt < 4; ++mt)
                    mma_tf32(acc[mt][nt],
                             afb[cur][mt][0].x, afb[cur][mt][1].x,
                             afb[cur][mt][0].y, afb[cur][mt][1].y,
                             bfb[cur][nt].x, bfb[cur][nt].y);
        }
    }

    // epilogue: bias + store
    const int pos0 = (t4 < 2) ? 4 * t4 : 4 * t4 - 7;   // kperm(2*t4); pos1 = pos0+2
    #pragma unroll
    for (int nt = 0; nt < 8; ++nt) {
        int cb = bCol + wc * 64 + nt * 8;
        float bx = bias[cb + 2 * t4], by = bias[cb + 2 * t4 + 1];
        #pragma unroll
        for (int mt = 0; mt < 4; ++mt) {
            int r0 = bRow + wr * 64 + mt * 16 + g;
            if (permute_out) {
                uint32_t* c0 = reinterpret_cast<uint32_t*>(C + (size_t)r0 * N + cb);
                uint32_t* c1 = reinterpret_cast<uint32_t*>(C + (size_t)(r0 + 8) * N + cb);
                c0[pos0]     = f2tf32(acc[mt][nt][0] + bx);
                c0[pos0 + 2] = f2tf32(acc[mt][nt][1] + by);
                c1[pos0]     = f2tf32(acc[mt][nt][2] + bx);
                c1[pos0 + 2] = f2tf32(acc[mt][nt][3] + by);
            } else {
                float2 v0 = make_float2(acc[mt][nt][0] + bx, acc[mt][nt][1] + by);
                float2 v1 = make_float2(acc[mt][nt][2] + bx, acc[mt][nt][3] + by);
                *reinterpret_cast<float2*>(C + (size_t)r0 * N + cb + 2 * t4)       = v0;
                *reinterpret_cast<float2*>(C + (size_t)(r0 + 8) * N + cb + 2 * t4) = v1;
            }
        }
    }
}

// ---------------------------------------------------------------------------
// Flash attention, tf32 mma.sync. Block = 128 queries (4 warps x 32q),
// 64-key tiles. qkv has d pair-permuted (flows through: Q@K^T invariant,
// V's permuted d makes the output emerge permuted for the proj GEMM).
// Q/K/P fragment loads are LDS.64; P stored key-pair-permuted.
// ---------------------------------------------------------------------------
#define AT_LD 72
#define ATT_SMEM_BYTES ((128 * AT_LD + 64 * AT_LD + 128 * AT_LD + 64 * AT_LD) * 4)

__global__ __launch_bounds__(128)
void attn_tf32_kernel(const float* __restrict__ qkv, float* __restrict__ out) {
    extern __shared__ uint32_t sm[];
    uint32_t* Qs = sm;                        // [128][AT_LD]
    uint32_t* Ks = Qs + 128 * AT_LD;          // [64][AT_LD]
    uint32_t* Ps = Ks + 64 * AT_LD;           // [128][AT_LD] key-permuted
    uint32_t* Vs = Ps + 128 * AT_LD;          // [64][AT_LD]

    const int qt = blockIdx.x;
    const int h  = blockIdx.y;
    const int b  = blockIdx.z;

    const int tid  = threadIdx.x;
    const int lane = tid & 31;
    const int wid  = tid >> 5;
    const int g    = lane >> 2;
    const int t4   = lane & 3;
    const int qw   = wid * 32;

    const float SC = 0.125f * 1.44269504088896341f;   // scale * log2(e)

    const int lrow = tid >> 4;                // 0..7
    const int lcol = (tid & 15) * 4;

    const uint32_t ks_b = (uint32_t)__cvta_generic_to_shared(Ks);
    const uint32_t vs_b = (uint32_t)__cvta_generic_to_shared(Vs);

    // Q: 128 rows, loaded once (scaled, re-rounded; permutation preserved by copy)
    {
        const float* qbase = qkv + ((size_t)(b * SEQ + qt * 128)) * QKVCOLS + h * HDIM;
        #pragma unroll
        for (int rr = lrow; rr < 128; rr += 8) {
            float4 q4 = *reinterpret_cast<const float4*>(qbase + (size_t)rr * QKVCOLS + lcol);
            Qs[rr * AT_LD + lcol + 0] = f2tf32(q4.x * SC);
            Qs[rr * AT_LD + lcol + 1] = f2tf32(q4.y * SC);
            Qs[rr * AT_LD + lcol + 2] = f2tf32(q4.z * SC);
            Qs[rr * AT_LD + lcol + 3] = f2tf32(q4.w * SC);
        }
    }

    float m_i[2][2], l_i[2][2];
    float oacc[2][8][4];
    #pragma unroll
    for (int mt = 0; mt < 2; ++mt) {
        m_i[mt][0] = m_i[mt][1] = -CUDART_INF_F;
        l_i[mt][0] = l_i[mt][1] = 0.0f;
        #pragma unroll
        for (int nt = 0; nt < 8; ++nt)
            #pragma unroll
            for (int r = 0; r < 4; ++r) oacc[mt][nt][r] = 0.0f;
    }

    const int pos0 = (t4 < 2) ? 4 * t4 : 4 * t4 - 7;   // kperm(2*t4)

    for (int t = 0; t < SEQ / 64; ++t) {
        __syncthreads();   // prior tile's reads done (covers Qs on t==0)

        {
            const float* kb_ = qkv + ((size_t)(b * SEQ + t * 64)) * QKVCOLS + DIM + h * HDIM;
            const float* vb_ = kb_ + DIM;
            #pragma unroll
            for (int rr = lrow; rr < 64; rr += 8) {
                cp16(ks_b + (uint32_t)(rr * AT_LD + lcol) * 4, kb_ + (size_t)rr * QKVCOLS + lcol);
                cp16(vs_b + (uint32_t)(rr * AT_LD + lcol) * 4, vb_ + (size_t)rr * QKVCOLS + lcol);
            }
            cp_commit();
            cp_wait0();
        }
        __syncthreads();

        // --- S = Q @ K^T ---
        float sacc[2][8][4];
        #pragma unroll
        for (int mt = 0; mt < 2; ++mt)
            #pragma unroll
            for (int nt = 0; nt < 8; ++nt)
                #pragma unroll
                for (int r = 0; r < 4; ++r) sacc[mt][nt][r] = 0.0f;

        #pragma unroll
        for (int ks = 0; ks < 8; ++ks) {
            const int k2 = ks * 8 + 2 * t4;
            uint2 af[2][2];
            #pragma unroll
            for (int mt = 0; mt < 2; ++mt) {
                int ab = (qw + mt * 16 + g) * AT_LD + k2;
                af[mt][0] = *reinterpret_cast<const uint2*>(&Qs[ab]);
                af[mt][1] = *reinterpret_cast<const uint2*>(&Qs[ab + 8 * AT_LD]);
            }
            #pragma unroll
            for (int nt = 0; nt < 8; ++nt) {
                uint2 bf = *reinterpret_cast<const uint2*>(&Ks[(nt * 8 + g) * AT_LD + k2]);
                #pragma unroll
                for (int mt = 0; mt < 2; ++mt)
                    mma_tf32(sacc[mt][nt],
                             af[mt][0].x, af[mt][1].x, af[mt][0].y, af[mt][1].y,
                             bf.x, bf.y);
            }
        }

        // --- online softmax (exp2 domain), P -> smem (key-pair-permuted) ---
        #pragma unroll
        for (int mt = 0; mt < 2; ++mt) {
            #pragma unroll
            for (int rh = 0; rh < 2; ++rh) {
                float mx = -CUDART_INF_F;
                #pragma unroll
                for (int nt = 0; nt < 8; ++nt)
                    mx = fmaxf(mx, fmaxf(sacc[mt][nt][rh * 2], sacc[mt][nt][rh * 2 + 1]));
                mx = fmaxf(mx, __shfl_xor_sync(0xffffffffu, mx, 1));
                mx = fmaxf(mx, __shfl_xor_sync(0xffffffffu, mx, 2));
                float mnew  = fmaxf(m_i[mt][rh], mx);
                float alpha = fexp2(m_i[mt][rh] - mnew);
                float rsum = 0.0f;
                int prow = (qw + mt * 16 + rh * 8 + g) * AT_LD;
                #pragma unroll
                for (int nt = 0; nt < 8; ++nt) {
                    float p0 = fexp2(sacc[mt][nt][rh * 2]     - mnew);
                    float p1 = fexp2(sacc[mt][nt][rh * 2 + 1] - mnew);
                    rsum += p0 + p1;
                    Ps[prow + nt * 8 + pos0]     = f2tf32(p0);
                    Ps[prow + nt * 8 + pos0 + 2] = f2tf32(p1);
                }
                rsum += __shfl_xor_sync(0xffffffffu, rsum, 1);
                rsum += __shfl_xor_sync(0xffffffffu, rsum, 2);
                l_i[mt][rh] = l_i[mt][rh] * alpha + rsum;
                m_i[mt][rh] = mnew;
                #pragma unroll
                for (int nt = 0; nt < 8; ++nt) {
                    oacc[mt][nt][rh * 2]     *= alpha;
                    oacc[mt][nt][rh * 2 + 1] *= alpha;
                }
            }
        }
        __syncwarp();   // P rows are warp-private

        // --- O += P @ V ---
        #pragma unroll
        for (int ks = 0; ks < 8; ++ks) {
            const int k2 = ks * 8 + 2 * t4;
            uint2 af[2][2];
            #pragma unroll
            for (int mt = 0; mt < 2; ++mt) {
                int ab = (qw + mt * 16 + g) * AT_LD + k2;
                af[mt][0] = *reinterpret_cast<const uint2*>(&Ps[ab]);
                af[mt][1] = *reinterpret_cast<const uint2*>(&Ps[ab + 8 * AT_LD]);
            }
            #pragma unroll
            for (int nt = 0; nt < 8; ++nt) {
                int bb = (ks * 8 + t4) * AT_LD + nt * 8 + g;
                uint32_t b0 = Vs[bb];
                uint32_t b1 = Vs[bb + 4 * AT_LD];
                #pragma unroll
                for (int mt = 0; mt < 2; ++mt)
                    mma_tf32(oacc[mt][nt],
                             af[mt][0].x, af[mt][1].x, af[mt][0].y, af[mt][1].y,
                             b0, b1);
            }
        }
    }

    // normalize + write tf32 bits (permuted layout inherited from V)
    #pragma unroll
    for (int mt = 0; mt < 2; ++mt) {
        #pragma unroll
        for (int rh = 0; rh < 2; ++rh) {
            float inv = 1.0f / l_i[mt][rh];
            size_t row = (size_t)(b * SEQ + qt * 128 + qw + mt * 16 + rh * 8 + g);
            #pragma unroll
            for (int nt = 0; nt < 8; ++nt) {
                float2 v;
                v.x = __uint_as_float(f2tf32(oacc[mt][nt][rh * 2]     * inv));
                v.y = __uint_as_float(f2tf32(oacc[mt][nt][rh * 2 + 1] * inv));
                *reinterpret_cast<float2*>(out + row * DIM + h * HDIM + nt * 8 + 2 * t4) = v;
            }
        }
    }
}

// ---------------------------------------------------------------------------
// Launch
// ---------------------------------------------------------------------------
extern "C" void kernel_launch(void* const* d_in, const int* in_sizes, int n_in,
                              void* d_out, int out_size) {
    const float* x      = (const float*)d_in[0];
    const float* w_qkv  = (const float*)d_in[1];
    const float* b_qkv  = (const float*)d_in[2];
    const float* w_proj = (const float*)d_in[3];
    const float* b_proj = (const float*)d_in[4];
    float* out = (float*)d_out;

    float *qkv, *attn, *xt, *w1, *w2;
    cudaGetSymbolAddress((void**)&qkv,  g_qkv);
    cudaGetSymbolAddress((void**)&attn, g_attn);
    cudaGetSymbolAddress((void**)&xt,   g_xt);
    cudaGetSymbolAddress((void**)&w1,   g_w1);
    cudaGetSymbolAddress((void**)&w2,   g_w2);

    cudaFuncSetAttribute(gemm_tf32_kernel,
                         cudaFuncAttributeMaxDynamicSharedMemorySize, GEMM_SMEM_BYTES);
    cudaFuncSetAttribute(attn_tf32_kernel,
                         cudaFuncAttributeMaxDynamicSharedMemorySize, ATT_SMEM_BYTES);

    // 0) prep: tf32 + k-pair-permute x; transpose+permute weights to [n][k]
    {
        int n4x = (MROWS * DIM) / 4;
        cvt_tf32_perm_kernel<<<(n4x + 255) / 256, 256>>>(x, xt, n4x);
        transpose_tf32_perm_kernel<<<dim3(QKVCOLS / 32, DIM / 32), 256>>>(w_qkv, w1, DIM, QKVCOLS);
        transpose_tf32_perm_kernel<<<dim3(DIM / 32, DIM / 32), 256>>>(w_proj, w2, DIM, DIM);
    }

    // 1) QKV projection (output permuted tf32 bits)
    gemm_tf32_kernel<<<dim3(QKVCOLS / 128, MROWS / 128), 128, GEMM_SMEM_BYTES>>>(
        xt, w1, b_qkv, qkv, MROWS, QKVCOLS, DIM, 1);

    // 2) Flash attention (output permuted tf32 bits)
    attn_tf32_kernel<<<dim3(SEQ / 128, HEADS, BATCH), 128, ATT_SMEM_BYTES>>>(qkv, attn);

    // 3) Output projection (logical fp32 output)
    gemm_tf32_kernel<<<dim3(DIM / 128, MROWS / 128), 128, GEMM_SMEM_BYTES>>>(
        attn, w2, b_proj, out, MROWS, DIM, DIM, 0);
}

// round 8
// speedup vs baseline: 1.1242x; 1.1242x over previous
#include <cuda_runtime.h>
#include <cuda_bf16.h>
#include <math_constants.h>
#include <cstdint>

// ---------------------------------------------------------------------------
// Problem constants
// ---------------------------------------------------------------------------
#define BATCH   8
#define SEQ     1024
#define DIM     768
#define HEADS   12
#define HDIM    64
#define MROWS   (BATCH * SEQ)        // 8192
#define QKVCOLS (3 * DIM)            // 2304

// Scratch (device globals per allocation rules)
__device__ float g_qkv[MROWS * QKVCOLS];     // [8192, 2304] tf32 bits
__device__ float g_attn[MROWS * DIM];        // [8192, 768]  tf32 bits
__device__ float g_xt[MROWS * DIM];          // x as tf32 bits
__device__ float g_w1[DIM * QKVCOLS];        // w_qkv tf32 bits
__device__ float g_w2[DIM * DIM];            // w_proj tf32 bits

// ---------------------------------------------------------------------------
// helpers
// ---------------------------------------------------------------------------
__device__ __forceinline__ uint32_t f2tf32(float x) {
    uint32_t r;
    asm("cvt.rna.tf32.f32 %0, %1;" : "=r"(r) : "f"(x));
    return r;
}
__device__ __forceinline__ float fexp2(float x) {
    float y;
    asm("ex2.approx.f32 %0, %1;" : "=f"(y) : "f"(x));
    return y;
}
__device__ __forceinline__ void mma_tf32(float c[4],
                                         uint32_t a0, uint32_t a1, uint32_t a2, uint32_t a3,
                                         uint32_t b0, uint32_t b1) {
    asm volatile(
        "mma.sync.aligned.m16n8k8.row.col.f32.tf32.tf32.f32 "
        "{%0,%1,%2,%3}, {%4,%5,%6,%7}, {%8,%9}, {%0,%1,%2,%3};\n"
        : "+f"(c[0]), "+f"(c[1]), "+f"(c[2]), "+f"(c[3])
        : "r"(a0), "r"(a1), "r"(a2), "r"(a3), "r"(b0), "r"(b1));
}
__device__ __forceinline__ void cp16(uint32_t dst_smem, const void* src) {
    asm volatile("cp.async.cg.shared.global [%0], [%1], 16;\n"
                 :: "r"(dst_smem), "l"(src) : "memory");
}
__device__ __forceinline__ void cp_commit() {
    asm volatile("cp.async.commit_group;\n" ::: "memory");
}
__device__ __forceinline__ void cp_wait0() {
    asm volatile("cp.async.wait_group 0;\n" ::: "memory");
}
__device__ __forceinline__ void cp_wait1() {
    asm volatile("cp.async.wait_group 1;\n" ::: "memory");
}

// ---------------------------------------------------------------------------
// tf32 pre-conversion (element-wise, float4)
// ---------------------------------------------------------------------------
__global__ __launch_bounds__(256)
void cvt_tf32_kernel(const float* __restrict__ in, float* __restrict__ out, int n4) {
    int i = blockIdx.x * 256 + threadIdx.x;
    if (i < n4) {
        float4 v = reinterpret_cast<const float4*>(in)[i];
        uint4 o;
        o.x = f2tf32(v.x); o.y = f2tf32(v.y); o.z = f2tf32(v.z); o.w = f2tf32(v.w);
        reinterpret_cast<uint4*>(out)[i] = o;
    }
}

// ---------------------------------------------------------------------------
// TF32 mma.sync GEMM + bias: C[M,N] = A[M,K]*B[K,N] + bias[N]
// A, B are PRE-CONVERTED tf32 bits. Block 128x128, 4 warps (2x2), warp 64x64,
// BK=32, cp.async THREE-stage pipeline (wait_group<=1) into MMA layouts:
//   A: [m][k] stride 36 (conflict-free stores + frag loads)
//   B: [k][n] stride 136
// store_tf32 != 0 -> output written as tf32 bits (for downstream MMA consumers)
// ---------------------------------------------------------------------------
#define GA_LDK 36
#define GB_LDN 136
#define G_AW   (128 * GA_LDK)       // 4608 words per A buffer
#define G_BW   (32 * GB_LDN)        // 4352 words per B buffer
#define GEMM_SMEM_BYTES ((3 * G_AW + 3 * G_BW) * 4)   // 107520

__global__ __launch_bounds__(128)
void gemm_tf32_kernel(const float* __restrict__ A,
                      const float* __restrict__ B,
                      const float* __restrict__ bias,
                      float* __restrict__ C,
                      int M, int N, int K, int store_tf32) {
    extern __shared__ uint32_t gsm[];
    const uint32_t sbytes = (uint32_t)__cvta_generic_to_shared(gsm);

    const int tid  = threadIdx.x;
    const int lane = tid & 31;
    const int wid  = tid >> 5;          // 0..3
    const int wr   = wid >> 1;          // 0..1 -> row base 64*wr
    const int wc   = wid & 1;           // 0..1 -> col base 64*wc
    const int g    = lane >> 2;         // 0..7
    const int t4   = lane & 3;          // 0..3

    const int bRow = blockIdx.y * 128;
    const int bCol = blockIdx.x * 128;

    auto issue_tile = [&](int buf, int kb) {
        const uint32_t abase = sbytes + (uint32_t)buf * G_AW * 4;
        const uint32_t bbase = sbytes + (uint32_t)(3 * G_AW + buf * G_BW) * 4;
        #pragma unroll
        for (int i = 0; i < 8; ++i) {
            int ch = tid + i * 128;
            int am = ch >> 3, ak = (ch & 7) * 4;        // A: 128 rows x 8 chunks
            cp16(abase + (uint32_t)(am * GA_LDK + ak) * 4,
                 A + (size_t)(bRow + am) * K + kb + ak);
            int bk = ch >> 5, bn = (ch & 31) * 4;        // B: 32 rows x 32 chunks
            cp16(bbase + (uint32_t)(bk * GB_LDN + bn) * 4,
                 B + (size_t)(kb + bk) * N + bCol + bn);
        }
        cp_commit();
    };

    float acc[4][8][4];
    #pragma unroll
    for (int mt = 0; mt < 4; ++mt)
        #pragma unroll
        for (int nt = 0; nt < 8; ++nt)
            #pragma unroll
            for (int r = 0; r < 4; ++r) acc[mt][nt][r] = 0.0f;

    const int NK = K / 32;              // 24
    issue_tile(0, 0);
    issue_tile(1, 32);

    int cur = 0;                         // buffer holding tile t
    for (int t = 0; t < NK; ++t) {
        cp_wait1();                      // tile t complete (t+1 may be in flight)
        __syncthreads();                 // visible to all; compute t-1 done everywhere
        if (t + 2 < NK) {
            int ahead = cur + 2; if (ahead >= 3) ahead -= 3;
            issue_tile(ahead, (t + 2) * 32);
        }

        const uint32_t* Ab = gsm + cur * G_AW;
        const uint32_t* Bb = gsm + 3 * G_AW + cur * G_BW;

        #pragma unroll
        for (int ks = 0; ks < 4; ++ks) {
            const int k0 = ks * 8;
            uint32_t af[4][4];
            #pragma unroll
            for (int mt = 0; mt < 4; ++mt) {
                int base = (wr * 64 + mt * 16 + g) * GA_LDK + k0 + t4;
                af[mt][0] = Ab[base];
                af[mt][1] = Ab[base + 8 * GA_LDK];
                af[mt][2] = Ab[base + 4];
                af[mt][3] = Ab[base + 8 * GA_LDK + 4];
            }
            #pragma unroll
            for (int nt = 0; nt < 8; ++nt) {
                int bb = (k0 + t4) * GB_LDN + wc * 64 + nt * 8 + g;
                uint32_t b0 = Bb[bb];
                uint32_t b1 = Bb[bb + 4 * GB_LDN];
                #pragma unroll
                for (int mt = 0; mt < 4; ++mt)
                    mma_tf32(acc[mt][nt], af[mt][0], af[mt][1], af[mt][2], af[mt][3],
                             b0, b1);
            }
        }

        if (++cur == 3) cur = 0;
    }

    // epilogue: bias + store
    #pragma unroll
    for (int nt = 0; nt < 8; ++nt) {
        int c = bCol + wc * 64 + nt * 8 + 2 * t4;
        float bx = bias[c], by = bias[c + 1];
        #pragma unroll
        for (int mt = 0; mt < 4; ++mt) {
            int r0 = bRow + wr * 64 + mt * 16 + g;
            float2 v0 = make_float2(acc[mt][nt][0] + bx, acc[mt][nt][1] + by);
            float2 v1 = make_float2(acc[mt][nt][2] + bx, acc[mt][nt][3] + by);
            if (store_tf32) {
                v0.x = __uint_as_float(f2tf32(v0.x));
                v0.y = __uint_as_float(f2tf32(v0.y));
                v1.x = __uint_as_float(f2tf32(v1.x));
                v1.y = __uint_as_float(f2tf32(v1.y));
            }
            *reinterpret_cast<float2*>(C + (size_t)r0 * N + c)       = v0;
            *reinterpret_cast<float2*>(C + (size_t)(r0 + 8) * N + c) = v1;
        }
    }
}

// ---------------------------------------------------------------------------
// Flash attention, tf32 mma.sync. Block = 128 queries (4 warps x 32q),
// 64-key tiles streamed via cp.async (KV already tf32 bits in g_qkv).
// Softmax in exp2 domain (log2e folded into Q scale). P stored as RAW fp32
// bits (tf32 mma reads the 19 MSBs -> deterministic truncation, saves CVTs).
// Output tf32 bits.
// ---------------------------------------------------------------------------
#define AQ_LD 68
#define AV_LD 72
#define ATT_SMEM_BYTES ((128 * AQ_LD + 64 * AQ_LD + 128 * AQ_LD + 64 * AV_LD) * 4)

__global__ __launch_bounds__(128)
void attn_tf32_kernel(const float* __restrict__ qkv, float* __restrict__ out) {
    extern __shared__ uint32_t sm[];
    uint32_t* Qs = sm;                        // [128][AQ_LD]
    uint32_t* Ks = Qs + 128 * AQ_LD;          // [64][AQ_LD]
    uint32_t* Ps = Ks + 64 * AQ_LD;           // [128][AQ_LD]
    uint32_t* Vs = Ps + 128 * AQ_LD;          // [64][AV_LD]

    const int qt = blockIdx.x;                // 128-query tile, 0..7
    const int h  = blockIdx.y;
    const int b  = blockIdx.z;

    const int tid  = threadIdx.x;
    const int lane = tid & 31;
    const int wid  = tid >> 5;                // 0..3
    const int g    = lane >> 2;
    const int t4   = lane & 3;
    const int qw   = wid * 32;                // warp's 32-query base

    const float SC = 0.125f * 1.44269504088896341f;   // scale * log2(e)

    const int lrow = tid >> 4;                // 0..7
    const int lcol = (tid & 15) * 4;

    const uint32_t ks_b = (uint32_t)__cvta_generic_to_shared(Ks);
    const uint32_t vs_b = (uint32_t)__cvta_generic_to_shared(Vs);

    // Q: 128 rows, loaded once (scaled, re-rounded to tf32)
    {
        const float* qbase = qkv + ((size_t)(b * SEQ + qt * 128)) * QKVCOLS + h * HDIM;
        #pragma unroll
        for (int rr = lrow; rr < 128; rr += 8) {
            float4 q4 = *reinterpret_cast<const float4*>(qbase + (size_t)rr * QKVCOLS + lcol);
            Qs[rr * AQ_LD + lcol + 0] = f2tf32(q4.x * SC);
            Qs[rr * AQ_LD + lcol + 1] = f2tf32(q4.y * SC);
            Qs[rr * AQ_LD + lcol + 2] = f2tf32(q4.z * SC);
            Qs[rr * AQ_LD + lcol + 3] = f2tf32(q4.w * SC);
        }
    }

    float m_i[2][2], l_i[2][2];
    float oacc[2][8][4];
    #pragma unroll
    for (int mt = 0; mt < 2; ++mt) {
        m_i[mt][0] = m_i[mt][1] = -CUDART_INF_F;
        l_i[mt][0] = l_i[mt][1] = 0.0f;
        #pragma unroll
        for (int nt = 0; nt < 8; ++nt)
            #pragma unroll
            for (int r = 0; r < 4; ++r) oacc[mt][nt][r] = 0.0f;
    }

    for (int t = 0; t < SEQ / 64; ++t) {
        __syncthreads();   // prior tile's PV reads done (covers Qs on t==0)

        // cp.async K and V tiles (already tf32 bits — straight copy)
        {
            const float* kb_ = qkv + ((size_t)(b * SEQ + t * 64)) * QKVCOLS + DIM + h * HDIM;
            const float* vb_ = kb_ + DIM;
            #pragma unroll
            for (int rr = lrow; rr < 64; rr += 8) {
                cp16(ks_b + (uint32_t)(rr * AQ_LD + lcol) * 4, kb_ + (size_t)rr * QKVCOLS + lcol);
                cp16(vs_b + (uint32_t)(rr * AV_LD + lcol) * 4, vb_ + (size_t)rr * QKVCOLS + lcol);
            }
            cp_commit();
            cp_wait0();
        }
        __syncthreads();

        // --- S = Q @ K^T  (32q x 64k per warp) ---
        float sacc[2][8][4];
        #pragma unroll
        for (int mt = 0; mt < 2; ++mt)
            #pragma unroll
            for (int nt = 0; nt < 8; ++nt)
                #pragma unroll
                for (int r = 0; r < 4; ++r) sacc[mt][nt][r] = 0.0f;

        #pragma unroll
        for (int ks = 0; ks < 8; ++ks) {
            uint32_t af[2][4];
            #pragma unroll
            for (int mt = 0; mt < 2; ++mt) {
                int ab = (qw + mt * 16 + g) * AQ_LD + ks * 8 + t4;
                af[mt][0] = Qs[ab];
                af[mt][1] = Qs[ab + 8 * AQ_LD];
                af[mt][2] = Qs[ab + 4];
                af[mt][3] = Qs[ab + 8 * AQ_LD + 4];
            }
            #pragma unroll
            for (int nt = 0; nt < 8; ++nt) {
                int bb = (nt * 8 + g) * AQ_LD + ks * 8 + t4;
                uint32_t b0 = Ks[bb];
                uint32_t b1 = Ks[bb + 4];
                #pragma unroll
                for (int mt = 0; mt < 2; ++mt)
                    mma_tf32(sacc[mt][nt], af[mt][0], af[mt][1], af[mt][2], af[mt][3],
                             b0, b1);
            }
        }

        // --- online softmax (exp2 domain), P -> smem (raw fp32 bits) ---
        #pragma unroll
        for (int mt = 0; mt < 2; ++mt) {
            #pragma unroll
            for (int rh = 0; rh < 2; ++rh) {
                float mx = -CUDART_INF_F;
                #pragma unroll
                for (int nt = 0; nt < 8; ++nt)
                    mx = fmaxf(mx, fmaxf(sacc[mt][nt][rh * 2], sacc[mt][nt][rh * 2 + 1]));
                mx = fmaxf(mx, __shfl_xor_sync(0xffffffffu, mx, 1));
                mx = fmaxf(mx, __shfl_xor_sync(0xffffffffu, mx, 2));
                float mnew  = fmaxf(m_i[mt][rh], mx);
                float alpha = fexp2(m_i[mt][rh] - mnew);
                float rsum = 0.0f;
                int prow = (qw + mt * 16 + rh * 8 + g) * AQ_LD;
                #pragma unroll
                for (int nt = 0; nt < 8; ++nt) {
                    float p0 = fexp2(sacc[mt][nt][rh * 2]     - mnew);
                    float p1 = fexp2(sacc[mt][nt][rh * 2 + 1] - mnew);
                    rsum += p0 + p1;
                    Ps[prow + nt * 8 + 2 * t4]     = __float_as_uint(p0);
                    Ps[prow + nt * 8 + 2 * t4 + 1] = __float_as_uint(p1);
                }
                rsum += __shfl_xor_sync(0xffffffffu, rsum, 1);
                rsum += __shfl_xor_sync(0xffffffffu, rsum, 2);
                l_i[mt][rh] = l_i[mt][rh] * alpha + rsum;
                m_i[mt][rh] = mnew;
                #pragma unroll
                for (int nt = 0; nt < 8; ++nt) {
                    oacc[mt][nt][rh * 2]     *= alpha;
                    oacc[mt][nt][rh * 2 + 1] *= alpha;
                }
            }
        }
        __syncwarp();   // P rows are warp-private

        // --- O += P @ V ---
        #pragma unroll
        for (int ks = 0; ks < 8; ++ks) {
            uint32_t af[2][4];
            #pragma unroll
            for (int mt = 0; mt < 2; ++mt) {
                int ab = (qw + mt * 16 + g) * AQ_LD + ks * 8 + t4;
                af[mt][0] = Ps[ab];
                af[mt][1] = Ps[ab + 8 * AQ_LD];
                af[mt][2] = Ps[ab + 4];
                af[mt][3] = Ps[ab + 8 * AQ_LD + 4];
            }
            #pragma unroll
            for (int nt = 0; nt < 8; ++nt) {
                int bb = (ks * 8 + t4) * AV_LD + nt * 8 + g;
                uint32_t b0 = Vs[bb];
                uint32_t b1 = Vs[bb + 4 * AV_LD];
                #pragma unroll
                for (int mt = 0; mt < 2; ++mt)
                    mma_tf32(oacc[mt][nt], af[mt][0], af[mt][1], af[mt][2], af[mt][3],
                             b0, b1);
            }
        }
    }

    // normalize + write tf32 bits to g_attn [B, N, C]
    #pragma unroll
    for (int mt = 0; mt < 2; ++mt) {
        #pragma unroll
        for (int rh = 0; rh < 2; ++rh) {
            float inv = 1.0f / l_i[mt][rh];
            size_t row = (size_t)(b * SEQ + qt * 128 + qw + mt * 16 + rh * 8 + g);
            #pragma unroll
            for (int nt = 0; nt < 8; ++nt) {
                float2 v;
                v.x = __uint_as_float(f2tf32(oacc[mt][nt][rh * 2]     * inv));
                v.y = __uint_as_float(f2tf32(oacc[mt][nt][rh * 2 + 1] * inv));
                *reinterpret_cast<float2*>(out + row * DIM + h * HDIM + nt * 8 + 2 * t4) = v;
            }
        }
    }
}

// ---------------------------------------------------------------------------
// Launch
// ---------------------------------------------------------------------------
extern "C" void kernel_launch(void* const* d_in, const int* in_sizes, int n_in,
                              void* d_out, int out_size) {
    const float* x      = (const float*)d_in[0];
    const float* w_qkv  = (const float*)d_in[1];
    const float* b_qkv  = (const float*)d_in[2];
    const float* w_proj = (const float*)d_in[3];
    const float* b_proj = (const float*)d_in[4];
    float* out = (float*)d_out;

    float *qkv, *attn, *xt, *w1, *w2;
    cudaGetSymbolAddress((void**)&qkv,  g_qkv);
    cudaGetSymbolAddress((void**)&attn, g_attn);
    cudaGetSymbolAddress((void**)&xt,   g_xt);
    cudaGetSymbolAddress((void**)&w1,   g_w1);
    cudaGetSymbolAddress((void**)&w2,   g_w2);

    cudaFuncSetAttribute(gemm_tf32_kernel,
                         cudaFuncAttributeMaxDynamicSharedMemorySize, GEMM_SMEM_BYTES);
    cudaFuncSetAttribute(attn_tf32_kernel,
                         cudaFuncAttributeMaxDynamicSharedMemorySize, ATT_SMEM_BYTES);

    // 0) pre-convert inputs/weights to tf32 bits
    {
        int n4x = (MROWS * DIM) / 4;
        cvt_tf32_kernel<<<(n4x + 255) / 256, 256>>>(x, xt, n4x);
        int n4w1 = (DIM * QKVCOLS) / 4;
        cvt_tf32_kernel<<<(n4w1 + 255) / 256, 256>>>(w_qkv, w1, n4w1);
        int n4w2 = (DIM * DIM) / 4;
        cvt_tf32_kernel<<<(n4w2 + 255) / 256, 256>>>(w_proj, w2, n4w2);
    }

    // 1) QKV projection (tf32-bit output for attention MMA consumers)
    gemm_tf32_kernel<<<dim3(QKVCOLS / 128, MROWS / 128), 128, GEMM_SMEM_BYTES>>>(
        xt, w1, b_qkv, qkv, MROWS, QKVCOLS, DIM, 1);

    // 2) Flash attention (tf32-bit output for proj GEMM)
    attn_tf32_kernel<<<dim3(SEQ / 128, HEADS, BATCH), 128, ATT_SMEM_BYTES>>>(qkv, attn);

    // 3) Output projection (plain fp32 output)
    gemm_tf32_kernel<<<dim3(DIM / 128, MROWS / 128), 128, GEMM_SMEM_BYTES>>>(
        attn, w2, b_proj, out, MROWS, DIM, DIM, 0);
}